// round 10
// baseline (speedup 1.0000x reference)
#include <cuda_runtime.h>
#include <cuda_fp16.h>
#include <cstdint>

// N=8192 tokens, D=128, x layout [8,384,32,32] fp32 (feature-major)
#define NTILES 64
#define SCALE 0.08838834764831845f  // 1/sqrt(128)

// byte offsets in dynamic smem; all fp16 tiles row=256B, XOR-swizzled 16B units
#define QB    0u        // Q  [m 64][k=feat 128]
#define K0B   16384u    // K  [n=token 128][k=feat 128] x2
#define K1B   49152u
#define V0B   81920u    // V  [v=feat 128][k=token 128] x2
#define V1B   114688u
#define P0B   147456u   // P  [m 64][k=key 128] x2
#define P1B   163840u
#define RS4B  180224u   // 64 x 4 f32 partial rowsums
#define RSB   181248u   // 64 f32 inverse rowsums
#define SMEM_BYTES 181504
#define RS4W  45056     // word indices
#define RSW   45312

extern __shared__ float smdyn[];

__device__ __forceinline__ uint32_t smem_u32(const void* p) {
    uint32_t a;
    asm("{ .reg .u64 t; cvta.to.shared.u64 t, %1; cvt.u32.u64 %0, t; }" : "=r"(a) : "l"(p));
    return a;
}
__device__ __forceinline__ void bar_sync(int id, int cnt) {
    asm volatile("bar.sync %0, %1;" :: "r"(id), "r"(cnt) : "memory");
}
__device__ __forceinline__ void bar_arrive(int id, int cnt) {
    asm volatile("bar.arrive %0, %1;" :: "r"(id), "r"(cnt) : "memory");
}
__device__ __forceinline__ uint32_t h2bits(float a, float b) {
    __half2 h = __floats2half2_rn(a, b);
    return *reinterpret_cast<uint32_t*>(&h);
}
__device__ __forceinline__ float h2sum(uint32_t u) {
    __half2 h = *reinterpret_cast<__half2*>(&u);
    float2 f = __half22float2(h);
    return f.x + f.y;
}
__device__ __forceinline__ void sts128(uint32_t a, uint32_t u0, uint32_t u1,
                                       uint32_t u2, uint32_t u3) {
    asm volatile("st.shared.v4.b32 [%0], {%1,%2,%3,%4};"
                 :: "r"(a), "r"(u0), "r"(u1), "r"(u2), "r"(u3) : "memory");
}
__device__ __forceinline__ void sts64(uint32_t a, uint32_t u0, uint32_t u1) {
    asm volatile("st.shared.v2.b32 [%0], {%1,%2};" :: "r"(a), "r"(u0), "r"(u1) : "memory");
}
__device__ __forceinline__ void sts32(uint32_t a, uint32_t u0) {
    asm volatile("st.shared.b32 [%0], %1;" :: "r"(a), "r"(u0) : "memory");
}
__device__ __forceinline__ void ldsm4(uint32_t r[4], uint32_t addr) {
    asm volatile("ldmatrix.sync.aligned.m8n8.x4.shared.b16 {%0,%1,%2,%3}, [%4];"
                 : "=r"(r[0]), "=r"(r[1]), "=r"(r[2]), "=r"(r[3]) : "r"(addr));
}
__device__ __forceinline__ void mma16(float c[4], const uint32_t a[4], const uint32_t b[2]) {
    asm volatile("mma.sync.aligned.m16n8k16.row.col.f32.f16.f16.f32 "
                 "{%0,%1,%2,%3}, {%4,%5,%6,%7}, {%8,%9}, {%0,%1,%2,%3};"
                 : "+f"(c[0]), "+f"(c[1]), "+f"(c[2]), "+f"(c[3])
                 : "r"(a[0]), "r"(a[1]), "r"(a[2]), "r"(a[3]),
                   "r"(b[0]), "r"(b[1]));
}

// ---- staging: gmem fp32 feature-major -> smem fp16, swizzled ----
// K: transpose-in-register. 64 jobs (tg 0..3 x fg 0..15), 8 per warp.
__device__ __forceinline__ void stage_K(const float* gk, uint32_t skb, int rank, int lane) {
#pragma unroll
    for (int i = 0; i < 8; i++) {
        int job = rank + 8 * i;
        int tg = job >> 4, fg = job & 15;
        int n = tg * 32 + lane;                 // token = smem row
        const float* gp = gk + (size_t)(fg * 8) * 1024 + n;
        float f[8];
#pragma unroll
        for (int j = 0; j < 8; j++) f[j] = gp[(size_t)j * 1024];
        uint32_t a = skb + (uint32_t)(n * 256 + ((fg ^ (n & 7)) << 4));
        sts128(a, h2bits(f[0], f[1]), h2bits(f[2], f[3]),
                  h2bits(f[4], f[5]), h2bits(f[6], f[7]));
    }
}
// V: feature rows are already k(token)-major. 16 rows per warp.
__device__ __forceinline__ void stage_V(const float* gv, uint32_t svb, int rank, int lane) {
#pragma unroll
    for (int i = 0; i < 16; i++) {
        int v = rank + 8 * i;
        float4 f = *(const float4*)(gv + (size_t)v * 1024 + 4 * lane);
        int u = lane >> 1;
        uint32_t a = svb + (uint32_t)(v * 256 + ((u ^ (v & 7)) << 4) + (lane & 1) * 8);
        sts64(a, h2bits(f.x, f.y), h2bits(f.z, f.w));
    }
}

__global__ void __launch_bounds__(512, 1)
conv_attn_kernel(const float* __restrict__ x, float* __restrict__ out) {
    const int tid  = threadIdx.x;
    const int lane = tid & 31;
    const int wid  = tid >> 5;
    const int g    = lane >> 2;
    const int t4   = lane & 3;
    const uint32_t sb = smem_u32(smdyn);
    float* smf = smdyn;

    const int bq  = blockIdx.x >> 4;
    const int sq0 = (blockIdx.x & 15) << 6;
    const float* Qg = x + (size_t)bq * 393216u + 262144u + sq0;

    // per-lane ldmatrix row decomposition (shared by all fragment groups)
    const int rowoff = ((lane >> 3) & 1) * 8 + (lane & 7);   // A-operand rows
    const int selA   = lane >> 4;                            // A k-half
    const int rowoffB = (lane >> 4) * 8 + (lane & 7);        // B-operand rows
    const int selB   = (lane >> 3) & 1;                      // B k-half
    const int sw     = lane & 7;                             // unit swizzle key

    // ---- prologue: stage Q (all 16 warps), K(0) by S half, V(0) by PV half ----
#pragma unroll
    for (int it = 0; it < 2; it++) {
        int job = wid + it * 16;                // 32 jobs: tg 0..1 x fg 0..15
        int tg = job >> 4, fg = job & 15;
        int m = tg * 32 + lane;
        const float* gp = Qg + (size_t)(fg * 8) * 1024 + m;
        float f[8];
#pragma unroll
        for (int j = 0; j < 8; j++) f[j] = gp[(size_t)j * 1024];
        uint32_t a = sb + QB + (uint32_t)(m * 256 + ((fg ^ (m & 7)) << 4));
        sts128(a, h2bits(f[0], f[1]), h2bits(f[2], f[3]),
                  h2bits(f[4], f[5]), h2bits(f[6], f[7]));
    }
    if (wid < 8) stage_K(x + 131072u, sb + K0B, wid, lane);
    else         stage_V(x,           sb + V0B, wid - 8, lane);
    __syncthreads();

    const uint32_t sK[2] = {sb + K0B, sb + K1B};
    const uint32_t sV[2] = {sb + V0B, sb + V1B};
    const uint32_t sP[2] = {sb + P0B, sb + P1B};

    if (wid < 8) {
        // ============ S GROUP: S = Q K^T, softmax -> P ============
        const int qrow = (wid >> 2) * 32;       // 2x4 grid of 32x32 tiles
        const int scol = (wid & 3) * 32;
        // fragment row bases
        const uint32_t qa0 = sb + QB + (uint32_t)((qrow + rowoff) * 256);
        const uint32_t qa1 = qa0 + 16 * 256;
        const uint32_t kb0off = (uint32_t)((scol + rowoffB) * 256);
        const uint32_t kb1off = kb0off + 16 * 256;

        float racc0[2] = {0.f, 0.f}, racc1[2] = {0.f, 0.f};

        for (int kt = 0; kt < NTILES; ++kt) {
            const int p = kt & 1;
            bar_sync(1, 256);                   // K(kt) staged

            float c[2][4][4];
#pragma unroll
            for (int mt = 0; mt < 2; mt++)
#pragma unroll
                for (int nt = 0; nt < 4; nt++)
#pragma unroll
                    for (int r = 0; r < 4; r++) c[mt][nt][r] = 0.f;

            const uint32_t kb0 = sK[p] + kb0off, kb1 = sK[p] + kb1off;
#pragma unroll
            for (int ks = 0; ks < 8; ks++) {
                const uint32_t ua = (uint32_t)(((2 * ks + selA) ^ sw) << 4);
                const uint32_t ub = (uint32_t)(((2 * ks + selB) ^ sw) << 4);
                uint32_t a0[4], a1[4], b0[4], b1[4];
                ldsm4(a0, qa0 + ua);
                ldsm4(a1, qa1 + ua);
                ldsm4(b0, kb0 + ub);
                ldsm4(b1, kb1 + ub);
                mma16(c[0][0], a0, b0 + 0); mma16(c[0][1], a0, b0 + 2);
                mma16(c[0][2], a0, b1 + 0); mma16(c[0][3], a0, b1 + 2);
                mma16(c[1][0], a1, b0 + 0); mma16(c[1][1], a1, b0 + 2);
                mma16(c[1][2], a1, b1 + 0); mma16(c[1][3], a1, b1 + 2);
            }

            if (kt + 1 < NTILES) {              // stage K(kt+1) into other buffer
                const int n = kt + 1;
                stage_K(x + (size_t)(n >> 3) * 393216u + 131072u + ((n & 7) << 7),
                        sK[1 - p], wid, lane);
            }
            if (kt >= 2) bar_sync(5 + p, 512);  // P buffer free

            // exp -> half2 -> P [m][k] swizzled; rowsum from packed values
            const uint32_t pb = sP[p];
#pragma unroll
            for (int mt = 0; mt < 2; mt++) {
                float s0 = 0.f, s1 = 0.f;
                const int row = qrow + mt * 16 + g;
#pragma unroll
                for (int nt = 0; nt < 4; nt++) {
                    float e0 = __expf(c[mt][nt][0] * SCALE);
                    float e1 = __expf(c[mt][nt][1] * SCALE);
                    float e2 = __expf(c[mt][nt][2] * SCALE);
                    float e3 = __expf(c[mt][nt][3] * SCALE);
                    uint32_t u01 = h2bits(e0, e1);
                    uint32_t u23 = h2bits(e2, e3);
                    s0 += h2sum(u01); s1 += h2sum(u23);
                    const int unit = (scol >> 3) + nt;
                    sts32(pb + (uint32_t)(row * 256 + ((unit ^ g) << 4) + 4 * t4), u01);
                    sts32(pb + (uint32_t)((row + 8) * 256 + ((unit ^ g) << 4) + 4 * t4), u23);
                }
                s0 += __shfl_xor_sync(0xffffffffu, s0, 1);
                s0 += __shfl_xor_sync(0xffffffffu, s0, 2);
                s1 += __shfl_xor_sync(0xffffffffu, s1, 1);
                s1 += __shfl_xor_sync(0xffffffffu, s1, 2);
                racc0[mt] += s0; racc1[mt] += s1;
            }
            bar_arrive(3 + p, 512);             // P(kt) full
        }

        if (t4 == 0) {
#pragma unroll
            for (int mt = 0; mt < 2; mt++) {
                const int row = qrow + mt * 16 + g;
                smf[RS4W + row * 4 + (wid & 3)]       = racc0[mt];
                smf[RS4W + (row + 8) * 4 + (wid & 3)] = racc1[mt];
            }
        }
        bar_arrive(3, 512);                     // rowsums ready
    } else {
        // ============ PV GROUP: O^T += V P^T ============
        const int wp   = wid - 8;
        const int vrow = (wp >> 1) * 32;        // 4x2 grid of 32x32 tiles
        const int mcol = (wp & 1) * 32;
        const int t256 = tid - 256;

        const uint32_t va0off = (uint32_t)((vrow + rowoff) * 256);
        const uint32_t va1off = va0off + 16 * 256;
        const uint32_t pb0off = (uint32_t)((mcol + rowoffB) * 256);
        const uint32_t pb1off = pb0off + 16 * 256;

        float o[2][4][4];
#pragma unroll
        for (int a = 0; a < 2; a++)
#pragma unroll
            for (int b = 0; b < 4; b++)
#pragma unroll
                for (int r = 0; r < 4; r++) o[a][b][r] = 0.f;

        for (int kt = 0; kt < NTILES; ++kt) {
            const int p = kt & 1;
            bar_sync(3 + p, 512);               // P(kt) ready
            bar_sync(2, 256);                   // V(kt) staged

            const uint32_t va0 = sV[p] + va0off, va1 = sV[p] + va1off;
            const uint32_t pbb0 = sP[p] + pb0off, pbb1 = sP[p] + pb1off;
#pragma unroll
            for (int ks = 0; ks < 8; ks++) {
                const uint32_t ua = (uint32_t)(((2 * ks + selA) ^ sw) << 4);
                const uint32_t ub = (uint32_t)(((2 * ks + selB) ^ sw) << 4);
                uint32_t a0[4], a1[4], b0[4], b1[4];
                ldsm4(a0, va0 + ua);
                ldsm4(a1, va1 + ua);
                ldsm4(b0, pbb0 + ub);
                ldsm4(b1, pbb1 + ub);
                mma16(o[0][0], a0, b0 + 0); mma16(o[0][1], a0, b0 + 2);
                mma16(o[0][2], a0, b1 + 0); mma16(o[0][3], a0, b1 + 2);
                mma16(o[1][0], a1, b0 + 0); mma16(o[1][1], a1, b0 + 2);
                mma16(o[1][2], a1, b1 + 0); mma16(o[1][3], a1, b1 + 2);
            }
            bar_arrive(5 + p, 512);             // P buffer free

            if (kt + 1 < NTILES) {
                const int n = kt + 1;
                stage_V(x + (size_t)(n >> 3) * 393216u + ((n & 7) << 7),
                        sV[1 - p], wp, lane);
            }
        }

        // ---- rowsums -> inverse, normalize, store ----
        bar_sync(3, 512);
        if (t256 < 64) {
            const float* r4 = smf + RS4W + t256 * 4;
            smf[RSW + t256] = 1.0f / (r4[0] + r4[1] + r4[2] + r4[3]);
        }
        bar_sync(2, 256);

        float* Og = out + (size_t)bq * 131072u + sq0;
#pragma unroll
        for (int bn = 0; bn < 4; bn++) {
            const int m0 = mcol + bn * 8 + 2 * t4;
            const float i0 = smf[RSW + m0], i1 = smf[RSW + m0 + 1];
#pragma unroll
            for (int vt = 0; vt < 2; vt++) {
                const int v = vrow + vt * 16 + g;
                *(float2*)(Og + (size_t)v * 1024 + m0) =
                    make_float2(o[vt][bn][0] * i0, o[vt][bn][1] * i1);
                *(float2*)(Og + (size_t)(v + 8) * 1024 + m0) =
                    make_float2(o[vt][bn][2] * i0, o[vt][bn][3] * i1);
            }
        }
    }
}

extern "C" void kernel_launch(void* const* d_in, const int* in_sizes, int n_in,
                              void* d_out, int out_size) {
    (void)in_sizes; (void)n_in; (void)out_size;
    const float* x = (const float*)d_in[0];
    float* out = (float*)d_out;
    cudaFuncSetAttribute(conv_attn_kernel,
                         cudaFuncAttributeMaxDynamicSharedMemorySize, SMEM_BYTES);
    conv_attn_kernel<<<128, 512, SMEM_BYTES>>>(x, out);
}

// round 11
// speedup vs baseline: 1.1768x; 1.1768x over previous
#include <cuda_runtime.h>
#include <cuda_fp16.h>
#include <cstdint>

// N=8192 tokens, D=128, x layout [8,384,32,32] fp32 (feature-major)
#define NTILES 64
#define SCALE 0.08838834764831845f  // 1/sqrt(128)

// byte offsets in dynamic smem; all fp16 tiles row=256B, XOR-swizzled 16B units
#define QB    0u        // Q  [m 64][k=feat 128]
#define K0B   16384u    // K  [n=token 128][k=feat 128] x2
#define K1B   49152u
#define V0B   81920u    // V  [v=feat 128][k=token 128] x2
#define V1B   114688u
#define P0B   147456u   // P  [m 64][k=key 128] x2
#define P1B   163840u
#define SMEM_BYTES 181504
#define RS4W  45056     // word idx: 64 x 2 partial rowsums
#define RSW   45312     // word idx: 64 inverse rowsums

extern __shared__ float smdyn[];

__device__ __forceinline__ uint32_t smem_u32(const void* p) {
    uint32_t a;
    asm("{ .reg .u64 t; cvta.to.shared.u64 t, %1; cvt.u32.u64 %0, t; }" : "=r"(a) : "l"(p));
    return a;
}
__device__ __forceinline__ void bar_sync(int id, int cnt) {
    asm volatile("bar.sync %0, %1;" :: "r"(id), "r"(cnt) : "memory");
}
__device__ __forceinline__ void bar_arrive(int id, int cnt) {
    asm volatile("bar.arrive %0, %1;" :: "r"(id), "r"(cnt) : "memory");
}
__device__ __forceinline__ uint32_t h2bits(float a, float b) {
    __half2 h = __floats2half2_rn(a, b);
    return *reinterpret_cast<uint32_t*>(&h);
}
__device__ __forceinline__ float h2sum(uint32_t u) {
    __half2 h = *reinterpret_cast<__half2*>(&u);
    float2 f = __half22float2(h);
    return f.x + f.y;
}
__device__ __forceinline__ void sts128(uint32_t a, uint32_t u0, uint32_t u1,
                                       uint32_t u2, uint32_t u3) {
    asm volatile("st.shared.v4.b32 [%0], {%1,%2,%3,%4};"
                 :: "r"(a), "r"(u0), "r"(u1), "r"(u2), "r"(u3) : "memory");
}
__device__ __forceinline__ void sts64(uint32_t a, uint32_t u0, uint32_t u1) {
    asm volatile("st.shared.v2.b32 [%0], {%1,%2};" :: "r"(a), "r"(u0), "r"(u1) : "memory");
}
__device__ __forceinline__ void sts32(uint32_t a, uint32_t u0) {
    asm volatile("st.shared.b32 [%0], %1;" :: "r"(a), "r"(u0) : "memory");
}
__device__ __forceinline__ void ldsm4(uint32_t r[4], uint32_t addr) {
    asm volatile("ldmatrix.sync.aligned.m8n8.x4.shared.b16 {%0,%1,%2,%3}, [%4];"
                 : "=r"(r[0]), "=r"(r[1]), "=r"(r[2]), "=r"(r[3]) : "r"(addr));
}
__device__ __forceinline__ void mma16(float c[4], const uint32_t a[4], const uint32_t b[2]) {
    asm volatile("mma.sync.aligned.m16n8k16.row.col.f32.f16.f16.f32 "
                 "{%0,%1,%2,%3}, {%4,%5,%6,%7}, {%8,%9}, {%0,%1,%2,%3};"
                 : "+f"(c[0]), "+f"(c[1]), "+f"(c[2]), "+f"(c[3])
                 : "r"(a[0]), "r"(a[1]), "r"(a[2]), "r"(a[3]),
                   "r"(b[0]), "r"(b[1]));
}

// ---- producer staging: gmem fp32 feature-major -> smem fp16, swizzled ----
// K: transpose-in-register (lane keeps its token). All LDGs batched for MLP.
__device__ __forceinline__ void stage_K(const float* gk, uint32_t skb, int rank, int lane) {
    float f[8][8];
    uint32_t addr[8];
#pragma unroll
    for (int i = 0; i < 8; i++) {
        int job = rank + 8 * i;
        int tg = job >> 4, fg = job & 15;
        int n = tg * 32 + lane;                 // token = smem row
        const float* gp = gk + (size_t)(fg * 8) * 1024 + n;
#pragma unroll
        for (int j = 0; j < 8; j++) f[i][j] = gp[(size_t)j * 1024];
        addr[i] = skb + (uint32_t)(n * 256 + ((fg ^ (n & 7)) << 4));
    }
#pragma unroll
    for (int i = 0; i < 8; i++)
        sts128(addr[i], h2bits(f[i][0], f[i][1]), h2bits(f[i][2], f[i][3]),
                        h2bits(f[i][4], f[i][5]), h2bits(f[i][6], f[i][7]));
}
// V: feature rows already token(k)-major; 16 independent LDG.128.
__device__ __forceinline__ void stage_V(const float* gv, uint32_t svb, int rank, int lane) {
    float4 f[16];
#pragma unroll
    for (int i = 0; i < 16; i++) {
        int v = rank + 8 * i;
        f[i] = *(const float4*)(gv + (size_t)v * 1024 + 4 * lane);
    }
    int u = lane >> 1;
#pragma unroll
    for (int i = 0; i < 16; i++) {
        int v = rank + 8 * i;
        uint32_t a = svb + (uint32_t)(v * 256 + ((u ^ (v & 7)) << 4) + (lane & 1) * 8);
        sts64(a, h2bits(f[i].x, f[i].y), h2bits(f[i].z, f[i].w));
    }
}

__global__ void __launch_bounds__(512, 1)
conv_attn_kernel(const float* __restrict__ x, float* __restrict__ out) {
    const int tid  = threadIdx.x;
    const int lane = tid & 31;
    const int wid  = tid >> 5;
    const int g    = lane >> 2;
    const int t4   = lane & 3;
    const uint32_t sb = smem_u32(smdyn);
    float* smf = smdyn;

    const int bq  = blockIdx.x >> 4;
    const int sq0 = (blockIdx.x & 15) << 6;
    const float* Qg = x + (size_t)bq * 393216u + 262144u + sq0;

    // ldmatrix per-lane decomposition
    const int rowoff  = ((lane >> 3) & 1) * 8 + (lane & 7);  // A rows
    const int selA    = lane >> 4;                           // A k-half
    const int rowoffB = (lane >> 4) * 8 + (lane & 7);        // B rows
    const int selB    = (lane >> 3) & 1;                     // B k-half
    const int sw      = lane & 7;

    const uint32_t sK[2] = {sb + K0B, sb + K1B};
    const uint32_t sV[2] = {sb + V0B, sb + V1B};
    const uint32_t sP[2] = {sb + P0B, sb + P1B};

    // ---- prologue: compute warps stage Q; producers stage K(0), V(0) ----
    if (wid < 8) {
#pragma unroll
        for (int it = 0; it < 4; it++) {
            int job = wid + 8 * it;              // 32 jobs: tg 0..1 x fg 0..15
            int tg = job >> 4, fg = job & 15;
            int m = tg * 32 + lane;
            const float* gp = Qg + (size_t)(fg * 8) * 1024 + m;
            float f[8];
#pragma unroll
            for (int j = 0; j < 8; j++) f[j] = gp[(size_t)j * 1024];
            uint32_t a = sb + QB + (uint32_t)(m * 256 + ((fg ^ (m & 7)) << 4));
            sts128(a, h2bits(f[0], f[1]), h2bits(f[2], f[3]),
                      h2bits(f[4], f[5]), h2bits(f[6], f[7]));
        }
    } else {
        stage_K(x + 131072u, sK[0], wid - 8, lane);
        stage_V(x,           sV[0], wid - 8, lane);
    }
    __syncthreads();

    if (wid < 4) {
        // ===== S GROUP (4 warps, 32x64 tiles): S = Q K^T, softmax -> P =====
        const int qrow = (wid >> 1) * 32;
        const int scol = (wid & 1) * 64;
        const uint32_t qa0 = sb + QB + (uint32_t)((qrow + rowoff) * 256);
        const uint32_t qa1 = qa0 + 16 * 256;
        const uint32_t kboff = (uint32_t)((scol + rowoffB) * 256);
        float racc0[2] = {0.f, 0.f}, racc1[2] = {0.f, 0.f};

        for (int kt = 0; kt < NTILES; ++kt) {
            const int p = kt & 1;
            if (kt > 0) bar_sync(1 + p, 384);    // K(kt) full

            float c[2][8][4];
#pragma unroll
            for (int mt = 0; mt < 2; mt++)
#pragma unroll
                for (int nt = 0; nt < 8; nt++)
#pragma unroll
                    for (int r = 0; r < 4; r++) c[mt][nt][r] = 0.f;

            const uint32_t kb = sK[p] + kboff;
#pragma unroll
            for (int ks = 0; ks < 8; ks++) {
                const uint32_t ua = (uint32_t)(((2 * ks + selA) ^ sw) << 4);
                const uint32_t ub = (uint32_t)(((2 * ks + selB) ^ sw) << 4);
                uint32_t a0[4], a1[4], b[4][4];
                ldsm4(a0, qa0 + ua);
                ldsm4(a1, qa1 + ua);
                ldsm4(b[0], kb + ub);
                ldsm4(b[1], kb + 16 * 256 + ub);
                ldsm4(b[2], kb + 32 * 256 + ub);
                ldsm4(b[3], kb + 48 * 256 + ub);
#pragma unroll
                for (int nb = 0; nb < 4; nb++) {
                    mma16(c[0][2 * nb],     a0, b[nb] + 0);
                    mma16(c[0][2 * nb + 1], a0, b[nb] + 2);
                    mma16(c[1][2 * nb],     a1, b[nb] + 0);
                    mma16(c[1][2 * nb + 1], a1, b[nb] + 2);
                }
            }
            bar_arrive(3 + p, 384);              // K(kt) free

            if (kt >= 2) bar_sync(11 + p, 256);  // P buffer free

            const uint32_t pb = sP[p];
#pragma unroll
            for (int mt = 0; mt < 2; mt++) {
                float s0 = 0.f, s1 = 0.f;
                const int row = qrow + mt * 16 + g;
#pragma unroll
                for (int nt = 0; nt < 8; nt++) {
                    float e0 = __expf(c[mt][nt][0] * SCALE);
                    float e1 = __expf(c[mt][nt][1] * SCALE);
                    float e2 = __expf(c[mt][nt][2] * SCALE);
                    float e3 = __expf(c[mt][nt][3] * SCALE);
                    uint32_t u01 = h2bits(e0, e1);
                    uint32_t u23 = h2bits(e2, e3);
                    s0 += h2sum(u01); s1 += h2sum(u23);
                    const int unit = (scol >> 3) + nt;
                    sts32(pb + (uint32_t)(row * 256 + ((unit ^ g) << 4) + 4 * t4), u01);
                    sts32(pb + (uint32_t)((row + 8) * 256 + ((unit ^ g) << 4) + 4 * t4), u23);
                }
                s0 += __shfl_xor_sync(0xffffffffu, s0, 1);
                s0 += __shfl_xor_sync(0xffffffffu, s0, 2);
                s1 += __shfl_xor_sync(0xffffffffu, s1, 1);
                s1 += __shfl_xor_sync(0xffffffffu, s1, 2);
                racc0[mt] += s0; racc1[mt] += s1;
            }
            bar_arrive(9 + p, 256);              // P(kt) full
        }

        if (t4 == 0) {
#pragma unroll
            for (int mt = 0; mt < 2; mt++) {
                const int row = qrow + mt * 16 + g;
                smf[RS4W + row * 2 + (wid & 1)]       = racc0[mt];
                smf[RS4W + (row + 8) * 2 + (wid & 1)] = racc1[mt];
            }
        }
        bar_arrive(13, 256);                     // rowsums ready
    } else if (wid < 8) {
        // ===== PV GROUP (4 warps, 64x32 tiles): O^T += V P^T =====
        const int wp   = wid - 4;
        const int vrow = (wp >> 1) * 64;
        const int mcol = (wp & 1) * 32;
        const int t128 = tid - 128;
        const uint32_t vaoff = (uint32_t)((vrow + rowoff) * 256);
        const uint32_t pboff = (uint32_t)((mcol + rowoffB) * 256);

        float o[4][4][4];
#pragma unroll
        for (int a = 0; a < 4; a++)
#pragma unroll
            for (int b = 0; b < 4; b++)
#pragma unroll
                for (int r = 0; r < 4; r++) o[a][b][r] = 0.f;

        for (int kt = 0; kt < NTILES; ++kt) {
            const int p = kt & 1;
            bar_sync(9 + p, 256);                // P(kt) full
            if (kt > 0) bar_sync(5 + p, 384);    // V(kt) full

            const uint32_t va = sV[p] + vaoff;
            const uint32_t pbb = sP[p] + pboff;
#pragma unroll
            for (int ks = 0; ks < 8; ks++) {
                const uint32_t ua = (uint32_t)(((2 * ks + selA) ^ sw) << 4);
                const uint32_t ub = (uint32_t)(((2 * ks + selB) ^ sw) << 4);
                uint32_t a[4][4], b0[4];
                ldsm4(a[0], va + ua);
                ldsm4(a[1], va + 16 * 256 + ua);
                ldsm4(a[2], va + 32 * 256 + ua);
                ldsm4(a[3], va + 48 * 256 + ua);
                ldsm4(b0, pbb + ub);
#pragma unroll
                for (int vt = 0; vt < 4; vt++) {
                    mma16(o[vt][0], a[vt], b0 + 0);
                    mma16(o[vt][1], a[vt], b0 + 2);
                }
                uint32_t b1[4];
                ldsm4(b1, pbb + 16 * 256 + ub);
#pragma unroll
                for (int vt = 0; vt < 4; vt++) {
                    mma16(o[vt][2], a[vt], b1 + 0);
                    mma16(o[vt][3], a[vt], b1 + 2);
                }
            }
            bar_arrive(7 + p, 384);              // V(kt) free
            bar_arrive(11 + p, 256);             // P(kt) free
        }

        // ---- rowsums -> inverse, normalize, store ----
        bar_sync(13, 256);
        if (t128 < 64) {
            const float* r2 = smf + RS4W + t128 * 2;
            smf[RSW + t128] = 1.0f / (r2[0] + r2[1]);
        }
        bar_sync(14, 128);

        float* Og = out + (size_t)bq * 131072u + sq0;
#pragma unroll
        for (int bn = 0; bn < 4; bn++) {
            const int m0 = mcol + bn * 8 + 2 * t4;
            const float i0 = smf[RSW + m0], i1 = smf[RSW + m0 + 1];
#pragma unroll
            for (int vt = 0; vt < 4; vt++) {
                const int v = vrow + vt * 16 + g;
                *(float2*)(Og + (size_t)v * 1024 + m0) =
                    make_float2(o[vt][bn][0] * i0, o[vt][bn][1] * i1);
                *(float2*)(Og + (size_t)(v + 8) * 1024 + m0) =
                    make_float2(o[vt][bn][2] * i0, o[vt][bn][3] * i1);
            }
        }
    } else {
        // ===== PRODUCER GROUP (8 warps): stage K(kt), V(kt) for kt>=1 =====
        const int pr = wid - 8;
        for (int kt = 1; kt < NTILES; ++kt) {
            const int p = kt & 1;
            const float* base = x + (size_t)(kt >> 3) * 393216u + ((kt & 7) << 7);
            if (kt >= 2) bar_sync(3 + p, 384);   // K buffer free
            stage_K(base + 131072u, sK[p], pr, lane);
            bar_arrive(1 + p, 384);              // K full
            if (kt >= 2) bar_sync(7 + p, 384);   // V buffer free
            stage_V(base, sV[p], pr, lane);
            bar_arrive(5 + p, 384);              // V full
        }
    }
}

extern "C" void kernel_launch(void* const* d_in, const int* in_sizes, int n_in,
                              void* d_out, int out_size) {
    (void)in_sizes; (void)n_in; (void)out_size;
    const float* x = (const float*)d_in[0];
    float* out = (float*)d_out;
    cudaFuncSetAttribute(conv_attn_kernel,
                         cudaFuncAttributeMaxDynamicSharedMemorySize, SMEM_BYTES);
    conv_attn_kernel<<<128, 512, SMEM_BYTES>>>(x, out);
}

// round 12
// speedup vs baseline: 1.5805x; 1.3430x over previous
#include <cuda_runtime.h>
#include <cuda_fp16.h>
#include <cstdint>

// N=8192 tokens, D=128, x layout [8,384,32,32] fp32 (feature-major)
#define NTILES 64
#define SCALE 0.08838834764831845f  // 1/sqrt(128)

// byte offsets in dynamic smem; all fp16 tiles row=256B, XOR-swizzled 16B units
#define QB    0u        // Q  [m 64][k=feat 128]
#define K0B   16384u    // K  [n=token 128][k=feat 128] x2
#define K1B   49152u
#define V0B   81920u    // V  [v=feat 128][k=token 128] x2
#define V1B   114688u
#define P0B   147456u   // P  [m 64][k=key 128] x2
#define P1B   163840u
#define SMEM_BYTES 181504
#define RS4W  45056     // word idx: 64 x 2 partial rowsums
#define RSW   45312     // word idx: 64 inverse rowsums

// one-time fp16 scratch (prepass output)
__device__ __half g_kt[8192 * 128];      // K^T: [token][feature], rows 256B
__device__ __half g_v[8 * 128 * 1024];   // V:   [batch][feature][token]

extern __shared__ float smdyn[];

__device__ __forceinline__ uint32_t smem_u32(const void* p) {
    uint32_t a;
    asm("{ .reg .u64 t; cvta.to.shared.u64 t, %1; cvt.u32.u64 %0, t; }" : "=r"(a) : "l"(p));
    return a;
}
__device__ __forceinline__ void bar_sync(int id, int cnt) {
    asm volatile("bar.sync %0, %1;" :: "r"(id), "r"(cnt) : "memory");
}
__device__ __forceinline__ void bar_arrive(int id, int cnt) {
    asm volatile("bar.arrive %0, %1;" :: "r"(id), "r"(cnt) : "memory");
}
__device__ __forceinline__ uint32_t h2bits(float a, float b) {
    __half2 h = __floats2half2_rn(a, b);
    return *reinterpret_cast<uint32_t*>(&h);
}
__device__ __forceinline__ float h2sum(uint32_t u) {
    __half2 h = *reinterpret_cast<__half2*>(&u);
    float2 f = __half22float2(h);
    return f.x + f.y;
}
__device__ __forceinline__ void sts128(uint32_t a, uint32_t u0, uint32_t u1,
                                       uint32_t u2, uint32_t u3) {
    asm volatile("st.shared.v4.b32 [%0], {%1,%2,%3,%4};"
                 :: "r"(a), "r"(u0), "r"(u1), "r"(u2), "r"(u3) : "memory");
}
__device__ __forceinline__ void sts32(uint32_t a, uint32_t u0) {
    asm volatile("st.shared.b32 [%0], %1;" :: "r"(a), "r"(u0) : "memory");
}
__device__ __forceinline__ void ldsm4(uint32_t r[4], uint32_t addr) {
    asm volatile("ldmatrix.sync.aligned.m8n8.x4.shared.b16 {%0,%1,%2,%3}, [%4];"
                 : "=r"(r[0]), "=r"(r[1]), "=r"(r[2]), "=r"(r[3]) : "r"(addr));
}
__device__ __forceinline__ void mma16(float c[4], const uint32_t a[4], const uint32_t b[2]) {
    asm volatile("mma.sync.aligned.m16n8k16.row.col.f32.f16.f16.f32 "
                 "{%0,%1,%2,%3}, {%4,%5,%6,%7}, {%8,%9}, {%0,%1,%2,%3};"
                 : "+f"(c[0]), "+f"(c[1]), "+f"(c[2]), "+f"(c[3])
                 : "r"(a[0]), "r"(a[1]), "r"(a[2]), "r"(a[3]),
                   "r"(b[0]), "r"(b[1]));
}
__device__ __forceinline__ void cp16h(uint32_t dst, const __half* src) {
    asm volatile("cp.async.cg.shared.global [%0], [%1], 16;" :: "r"(dst), "l"(src));
}
__device__ __forceinline__ void cp_commit() { asm volatile("cp.async.commit_group;"); }
__device__ __forceinline__ void cp_wait0()  { asm volatile("cp.async.wait_group 0;"); }
__device__ __forceinline__ void cp_wait1()  { asm volatile("cp.async.wait_group 1;"); }

// ================= prepass: x fp32 -> fp16 scratch (K transposed) =================
__global__ void __launch_bounds__(256) prepass_kernel(const float* __restrict__ x) {
    const int tid  = blockIdx.x * 256 + threadIdx.x;   // 0..16383
    const int wid  = tid >> 5;                          // 0..511
    const int lane = threadIdx.x & 31;

    // K transpose: 4096 warp-jobs (token-block 0..255 x feature-group 0..15)
#pragma unroll
    for (int i = 0; i < 8; i++) {
        int job = wid * 8 + i;
        int tb = job >> 4, fg = job & 15;
        int b = tb >> 5;
        int t = (tb & 31) * 32 + lane;
        const float* gp = x + (size_t)b * 393216u + (size_t)(128 + fg * 8) * 1024u + t;
        float f[8];
#pragma unroll
        for (int j = 0; j < 8; j++) f[j] = gp[(size_t)j * 1024];
        uint4 u;
        u.x = h2bits(f[0], f[1]); u.y = h2bits(f[2], f[3]);
        u.z = h2bits(f[4], f[5]); u.w = h2bits(f[6], f[7]);
        *(uint4*)(&g_kt[(size_t)((b * 1024 + t) * 128 + fg * 8)]) = u;
    }

    // V convert: 1,048,576 floats -> halves, 8 per iter per thread
#pragma unroll
    for (int i = 0; i < 8; i++) {
        int e = (i * 16384 + tid) * 8;
        int b = e >> 17;
        int r = e & 131071;
        const float* gp = x + (size_t)b * 393216u + r;
        float4 a0 = *(const float4*)gp;
        float4 a1 = *(const float4*)(gp + 4);
        uint4 u;
        u.x = h2bits(a0.x, a0.y); u.y = h2bits(a0.z, a0.w);
        u.z = h2bits(a1.x, a1.y); u.w = h2bits(a1.z, a1.w);
        *(uint4*)(&g_v[e]) = u;
    }
}

// ---- producer staging: cp.async fp16 scratch -> swizzled smem ----
__device__ __forceinline__ void stage_K_async(int kt, uint32_t skb, int pr, int lane) {
#pragma unroll
    for (int i = 0; i < 8; i++) {
        int id = pr * 256 + i * 32 + lane;      // 0..2047 16B-units
        int n = id >> 4, fg = id & 15;
        cp16h(skb + (uint32_t)(n * 256 + ((fg ^ (n & 7)) << 4)),
              g_kt + (size_t)((kt * 128 + n) * 128 + fg * 8));
    }
}
__device__ __forceinline__ void stage_V_async(int kt, uint32_t svb, int pr, int lane) {
    const int bv = kt >> 3, tof = (kt & 7) << 7;
#pragma unroll
    for (int i = 0; i < 8; i++) {
        int id = pr * 256 + i * 32 + lane;
        int v = id >> 4, u = id & 15;
        cp16h(svb + (uint32_t)(v * 256 + ((u ^ (v & 7)) << 4)),
              g_v + (size_t)((bv * 128 + v) * 1024 + tof + u * 8));
    }
}

__global__ void __launch_bounds__(512, 1)
conv_attn_kernel(const float* __restrict__ x, float* __restrict__ out) {
    const int tid  = threadIdx.x;
    const int lane = tid & 31;
    const int wid  = tid >> 5;
    const int g    = lane >> 2;
    const int t4   = lane & 3;
    const uint32_t sb = smem_u32(smdyn);
    float* smf = smdyn;

    const int bq  = blockIdx.x >> 4;
    const int sq0 = (blockIdx.x & 15) << 6;
    const float* Qg = x + (size_t)bq * 393216u + 262144u + sq0;

    // ldmatrix per-lane decomposition
    const int rowoff  = ((lane >> 3) & 1) * 8 + (lane & 7);  // A rows
    const int selA    = lane >> 4;                           // A k-half
    const int rowoffB = (lane >> 4) * 8 + (lane & 7);        // B rows
    const int selB    = (lane >> 3) & 1;                     // B k-half
    const int sw      = lane & 7;

    const uint32_t sK[2] = {sb + K0B, sb + K1B};
    const uint32_t sV[2] = {sb + V0B, sb + V1B};
    const uint32_t sP[2] = {sb + P0B, sb + P1B};

    // ---- prologue: compute warps stage Q; producers cp.async K(0), V(0) ----
    if (wid < 8) {
#pragma unroll
        for (int it = 0; it < 4; it++) {
            int job = wid + 8 * it;              // 32 jobs: tg 0..1 x fg 0..15
            int tg = job >> 4, fg = job & 15;
            int m = tg * 32 + lane;
            const float* gp = Qg + (size_t)(fg * 8) * 1024 + m;
            float f[8];
#pragma unroll
            for (int j = 0; j < 8; j++) f[j] = gp[(size_t)j * 1024];
            uint32_t a = sb + QB + (uint32_t)(m * 256 + ((fg ^ (m & 7)) << 4));
            sts128(a, h2bits(f[0], f[1]), h2bits(f[2], f[3]),
                      h2bits(f[4], f[5]), h2bits(f[6], f[7]));
        }
    } else {
        stage_K_async(0, sK[0], wid - 8, lane);
        cp_commit();
        stage_V_async(0, sV[0], wid - 8, lane);
        cp_commit();
        cp_wait0();
    }
    __syncthreads();

    if (wid < 4) {
        // ===== S GROUP (4 warps, 32x64 tiles): S = Q K^T, softmax -> P =====
        const int qrow = (wid >> 1) * 32;
        const int scol = (wid & 1) * 64;
        const uint32_t qa0 = sb + QB + (uint32_t)((qrow + rowoff) * 256);
        const uint32_t qa1 = qa0 + 16 * 256;
        const uint32_t kboff = (uint32_t)((scol + rowoffB) * 256);
        float racc0[2] = {0.f, 0.f}, racc1[2] = {0.f, 0.f};

        for (int kt = 0; kt < NTILES; ++kt) {
            const int p = kt & 1;
            if (kt > 0) bar_sync(1 + p, 384);    // K(kt) full

            float c[2][8][4];
#pragma unroll
            for (int mt = 0; mt < 2; mt++)
#pragma unroll
                for (int nt = 0; nt < 8; nt++)
#pragma unroll
                    for (int r = 0; r < 4; r++) c[mt][nt][r] = 0.f;

            const uint32_t kb = sK[p] + kboff;
#pragma unroll
            for (int ks = 0; ks < 8; ks++) {
                const uint32_t ua = (uint32_t)(((2 * ks + selA) ^ sw) << 4);
                const uint32_t ub = (uint32_t)(((2 * ks + selB) ^ sw) << 4);
                uint32_t a0[4], a1[4], b[4][4];
                ldsm4(a0, qa0 + ua);
                ldsm4(a1, qa1 + ua);
                ldsm4(b[0], kb + ub);
                ldsm4(b[1], kb + 16 * 256 + ub);
                ldsm4(b[2], kb + 32 * 256 + ub);
                ldsm4(b[3], kb + 48 * 256 + ub);
#pragma unroll
                for (int nb = 0; nb < 4; nb++) {
                    mma16(c[0][2 * nb],     a0, b[nb] + 0);
                    mma16(c[0][2 * nb + 1], a0, b[nb] + 2);
                    mma16(c[1][2 * nb],     a1, b[nb] + 0);
                    mma16(c[1][2 * nb + 1], a1, b[nb] + 2);
                }
            }
            bar_arrive(3 + p, 384);              // K(kt) free

            if (kt >= 2) bar_sync(11 + p, 256);  // P buffer free

            const uint32_t pb = sP[p];
#pragma unroll
            for (int mt = 0; mt < 2; mt++) {
                float s0 = 0.f, s1 = 0.f;
                const int row = qrow + mt * 16 + g;
#pragma unroll
                for (int nt = 0; nt < 8; nt++) {
                    float e0 = __expf(c[mt][nt][0] * SCALE);
                    float e1 = __expf(c[mt][nt][1] * SCALE);
                    float e2 = __expf(c[mt][nt][2] * SCALE);
                    float e3 = __expf(c[mt][nt][3] * SCALE);
                    uint32_t u01 = h2bits(e0, e1);
                    uint32_t u23 = h2bits(e2, e3);
                    s0 += h2sum(u01); s1 += h2sum(u23);
                    const int unit = (scol >> 3) + nt;
                    sts32(pb + (uint32_t)(row * 256 + ((unit ^ g) << 4) + 4 * t4), u01);
                    sts32(pb + (uint32_t)((row + 8) * 256 + ((unit ^ g) << 4) + 4 * t4), u23);
                }
                s0 += __shfl_xor_sync(0xffffffffu, s0, 1);
                s0 += __shfl_xor_sync(0xffffffffu, s0, 2);
                s1 += __shfl_xor_sync(0xffffffffu, s1, 1);
                s1 += __shfl_xor_sync(0xffffffffu, s1, 2);
                racc0[mt] += s0; racc1[mt] += s1;
            }
            bar_arrive(9 + p, 256);              // P(kt) full
        }

        if (t4 == 0) {
#pragma unroll
            for (int mt = 0; mt < 2; mt++) {
                const int row = qrow + mt * 16 + g;
                smf[RS4W + row * 2 + (wid & 1)]       = racc0[mt];
                smf[RS4W + (row + 8) * 2 + (wid & 1)] = racc1[mt];
            }
        }
        bar_arrive(13, 256);                     // rowsums ready
    } else if (wid < 8) {
        // ===== PV GROUP (4 warps, 64x32 tiles): O^T += V P^T =====
        const int wp   = wid - 4;
        const int vrow = (wp >> 1) * 64;
        const int mcol = (wp & 1) * 32;
        const int t128 = tid - 128;
        const uint32_t vaoff = (uint32_t)((vrow + rowoff) * 256);
        const uint32_t pboff = (uint32_t)((mcol + rowoffB) * 256);

        float o[4][4][4];
#pragma unroll
        for (int a = 0; a < 4; a++)
#pragma unroll
            for (int b = 0; b < 4; b++)
#pragma unroll
                for (int r = 0; r < 4; r++) o[a][b][r] = 0.f;

        for (int kt = 0; kt < NTILES; ++kt) {
            const int p = kt & 1;
            bar_sync(9 + p, 256);                // P(kt) full
            if (kt > 0) bar_sync(5 + p, 384);    // V(kt) full

            const uint32_t va = sV[p] + vaoff;
            const uint32_t pbb = sP[p] + pboff;
#pragma unroll
            for (int ks = 0; ks < 8; ks++) {
                const uint32_t ua = (uint32_t)(((2 * ks + selA) ^ sw) << 4);
                const uint32_t ub = (uint32_t)(((2 * ks + selB) ^ sw) << 4);
                uint32_t a[4][4], b0[4];
                ldsm4(a[0], va + ua);
                ldsm4(a[1], va + 16 * 256 + ua);
                ldsm4(a[2], va + 32 * 256 + ua);
                ldsm4(a[3], va + 48 * 256 + ua);
                ldsm4(b0, pbb + ub);
#pragma unroll
                for (int vt = 0; vt < 4; vt++) {
                    mma16(o[vt][0], a[vt], b0 + 0);
                    mma16(o[vt][1], a[vt], b0 + 2);
                }
                uint32_t b1[4];
                ldsm4(b1, pbb + 16 * 256 + ub);
#pragma unroll
                for (int vt = 0; vt < 4; vt++) {
                    mma16(o[vt][2], a[vt], b1 + 0);
                    mma16(o[vt][3], a[vt], b1 + 2);
                }
            }
            bar_arrive(7 + p, 384);              // V(kt) free
            bar_arrive(11 + p, 256);             // P(kt) free
        }

        // ---- rowsums -> inverse, normalize, store ----
        bar_sync(13, 256);
        if (t128 < 64) {
            const float* r2 = smf + RS4W + t128 * 2;
            smf[RSW + t128] = 1.0f / (r2[0] + r2[1]);
        }
        bar_sync(14, 128);

        float* Og = out + (size_t)bq * 131072u + sq0;
#pragma unroll
        for (int bn = 0; bn < 4; bn++) {
            const int m0 = mcol + bn * 8 + 2 * t4;
            const float i0 = smf[RSW + m0], i1 = smf[RSW + m0 + 1];
#pragma unroll
            for (int vt = 0; vt < 4; vt++) {
                const int v = vrow + vt * 16 + g;
                *(float2*)(Og + (size_t)v * 1024 + m0) =
                    make_float2(o[vt][bn][0] * i0, o[vt][bn][1] * i1);
                *(float2*)(Og + (size_t)(v + 8) * 1024 + m0) =
                    make_float2(o[vt][bn][2] * i0, o[vt][bn][3] * i1);
            }
        }
    } else {
        // ===== PRODUCER GROUP (8 warps): cp.async K(kt), V(kt) for kt>=1 =====
        const int pr = wid - 8;
        for (int kt = 1; kt < NTILES; ++kt) {
            const int p = kt & 1;
            if (kt >= 2) bar_sync(3 + p, 384);   // K buffer free
            stage_K_async(kt, sK[p], pr, lane);
            cp_commit();
            if (kt >= 2) bar_sync(7 + p, 384);   // V buffer free
            stage_V_async(kt, sV[p], pr, lane);
            cp_commit();
            cp_wait1();                          // K batch landed
            bar_arrive(1 + p, 384);              // K full
            cp_wait0();                          // V batch landed
            bar_arrive(5 + p, 384);              // V full
        }
    }
}

extern "C" void kernel_launch(void* const* d_in, const int* in_sizes, int n_in,
                              void* d_out, int out_size) {
    (void)in_sizes; (void)n_in; (void)out_size;
    const float* x = (const float*)d_in[0];
    float* out = (float*)d_out;
    cudaFuncSetAttribute(conv_attn_kernel,
                         cudaFuncAttributeMaxDynamicSharedMemorySize, SMEM_BYTES);
    prepass_kernel<<<64, 256>>>(x);
    conv_attn_kernel<<<128, 512, SMEM_BYTES>>>(x, out);
}

// round 13
// speedup vs baseline: 1.6080x; 1.0174x over previous
#include <cuda_runtime.h>
#include <cuda_fp16.h>
#include <cstdint>

// N=8192 tokens, D=128, x layout [8,384,32,32] fp32 (feature-major)
#define NTILES 64
#define SCALE 0.08838834764831845f  // 1/sqrt(128)

// byte offsets in dynamic smem; all fp16 tiles row=256B, XOR-swizzled 16B units
#define QB    0u        // Q  [m 64][k=feat 128]
#define KAB   16384u    // K group A
#define KBB   49152u    // K group B
#define VAB   81920u    // V group A
#define VBB   114688u   // V group B
#define PAB   147456u   // P group A [m 64][k 128]
#define PBB   163840u   // P group B
#define SMEM_BYTES 181504
#define RS4W  45056     // word idx: 64 x 4 partial rowsums (A0,A1,B0,B1)
#define RSW   45312     // word idx: 64 inverse rowsums
#define OCW   4096      // word idx: epilogue O-combine scratch (reuses K buffers)
#define OST   68        // O-combine row stride (floats)

// one-time fp16 scratch (prepass output)
__device__ __half g_kt[8192 * 128];      // K^T: [token][feature]
__device__ __half g_v[8 * 128 * 1024];   // V:   [batch][feature][token]

extern __shared__ float smdyn[];

__device__ __forceinline__ uint32_t smem_u32(const void* p) {
    uint32_t a;
    asm("{ .reg .u64 t; cvta.to.shared.u64 t, %1; cvt.u32.u64 %0, t; }" : "=r"(a) : "l"(p));
    return a;
}
__device__ __forceinline__ void bar_sync(int id, int cnt) {
    asm volatile("bar.sync %0, %1;" :: "r"(id), "r"(cnt) : "memory");
}
__device__ __forceinline__ void bar_arrive(int id, int cnt) {
    asm volatile("bar.arrive %0, %1;" :: "r"(id), "r"(cnt) : "memory");
}
__device__ __forceinline__ uint32_t h2bits(float a, float b) {
    __half2 h = __floats2half2_rn(a, b);
    return *reinterpret_cast<uint32_t*>(&h);
}
__device__ __forceinline__ float h2sum(uint32_t u) {
    __half2 h = *reinterpret_cast<__half2*>(&u);
    float2 f = __half22float2(h);
    return f.x + f.y;
}
__device__ __forceinline__ void sts128(uint32_t a, uint32_t u0, uint32_t u1,
                                       uint32_t u2, uint32_t u3) {
    asm volatile("st.shared.v4.b32 [%0], {%1,%2,%3,%4};"
                 :: "r"(a), "r"(u0), "r"(u1), "r"(u2), "r"(u3) : "memory");
}
__device__ __forceinline__ void sts32(uint32_t a, uint32_t u0) {
    asm volatile("st.shared.b32 [%0], %1;" :: "r"(a), "r"(u0) : "memory");
}
__device__ __forceinline__ void ldsm4(uint32_t r[4], uint32_t addr) {
    asm volatile("ldmatrix.sync.aligned.m8n8.x4.shared.b16 {%0,%1,%2,%3}, [%4];"
                 : "=r"(r[0]), "=r"(r[1]), "=r"(r[2]), "=r"(r[3]) : "r"(addr));
}
__device__ __forceinline__ void mma16(float c[4], const uint32_t a[4], const uint32_t b[2]) {
    asm volatile("mma.sync.aligned.m16n8k16.row.col.f32.f16.f16.f32 "
                 "{%0,%1,%2,%3}, {%4,%5,%6,%7}, {%8,%9}, {%0,%1,%2,%3};"
                 : "+f"(c[0]), "+f"(c[1]), "+f"(c[2]), "+f"(c[3])
                 : "r"(a[0]), "r"(a[1]), "r"(a[2]), "r"(a[3]),
                   "r"(b[0]), "r"(b[1]));
}
__device__ __forceinline__ void cp16h(uint32_t dst, const __half* src) {
    asm volatile("cp.async.cg.shared.global [%0], [%1], 16;" :: "r"(dst), "l"(src));
}
__device__ __forceinline__ void cp_commit() { asm volatile("cp.async.commit_group;"); }
__device__ __forceinline__ void cp_wait0()  { asm volatile("cp.async.wait_group 0;"); }

// ================= prepass: x fp32 -> fp16 scratch (K transposed) =================
__global__ void __launch_bounds__(256) prepass_kernel(const float* __restrict__ x) {
    const int tid  = blockIdx.x * 256 + threadIdx.x;   // 0..16383
    const int wid  = tid >> 5;                          // 0..511
    const int lane = threadIdx.x & 31;

#pragma unroll
    for (int i = 0; i < 8; i++) {
        int job = wid * 8 + i;
        int tb = job >> 4, fg = job & 15;
        int b = tb >> 5;
        int t = (tb & 31) * 32 + lane;
        const float* gp = x + (size_t)b * 393216u + (size_t)(128 + fg * 8) * 1024u + t;
        float f[8];
#pragma unroll
        for (int j = 0; j < 8; j++) f[j] = gp[(size_t)j * 1024];
        uint4 u;
        u.x = h2bits(f[0], f[1]); u.y = h2bits(f[2], f[3]);
        u.z = h2bits(f[4], f[5]); u.w = h2bits(f[6], f[7]);
        *(uint4*)(&g_kt[(size_t)((b * 1024 + t) * 128 + fg * 8)]) = u;
    }
#pragma unroll
    for (int i = 0; i < 8; i++) {
        int e = (i * 16384 + tid) * 8;
        int b = e >> 17;
        int r = e & 131071;
        const float* gp = x + (size_t)b * 393216u + r;
        float4 a0 = *(const float4*)gp;
        float4 a1 = *(const float4*)(gp + 4);
        uint4 u;
        u.x = h2bits(a0.x, a0.y); u.y = h2bits(a0.z, a0.w);
        u.z = h2bits(a1.x, a1.y); u.w = h2bits(a1.z, a1.w);
        *(uint4*)(&g_v[e]) = u;
    }
}

// ---- staging: cp.async fp16 scratch -> swizzled smem (4 warps per array) ----
__device__ __forceinline__ void stage_K_async(int kt, uint32_t skb, int pr, int lane) {
#pragma unroll
    for (int i = 0; i < 16; i++) {
        int id = pr * 512 + i * 32 + lane;      // 0..2047 16B-units
        int n = id >> 4, fg = id & 15;
        cp16h(skb + (uint32_t)(n * 256 + ((fg ^ (n & 7)) << 4)),
              g_kt + (size_t)((kt * 128 + n) * 128 + fg * 8));
    }
}
__device__ __forceinline__ void stage_V_async(int kt, uint32_t svb, int pr, int lane) {
    const int bv = kt >> 3, tof = (kt & 7) << 7;
#pragma unroll
    for (int i = 0; i < 16; i++) {
        int id = pr * 512 + i * 32 + lane;
        int v = id >> 4, u = id & 15;
        cp16h(svb + (uint32_t)(v * 256 + ((u ^ (v & 7)) << 4)),
              g_v + (size_t)((bv * 128 + v) * 1024 + tof + u * 8));
    }
}

__global__ void __launch_bounds__(512, 1)
conv_attn_kernel(const float* __restrict__ x, float* __restrict__ out) {
    const int tid  = threadIdx.x;
    const int lane = tid & 31;
    const int wid  = tid >> 5;
    const int g    = lane >> 2;
    const int t4   = lane & 3;
    const uint32_t sb = smem_u32(smdyn);
    float* smf = smdyn;

    const int g01  = wid >> 3;                 // 0 = group A (even kt), 1 = B (odd kt)
    const int w4   = wid & 3;
    const bool isS = (wid & 7) < 4;

    const int bq  = blockIdx.x >> 4;
    const int sq0 = (blockIdx.x & 15) << 6;
    const float* Qg = x + (size_t)bq * 393216u + 262144u + sq0;

    // ldmatrix per-lane decomposition
    const int rowoff  = ((lane >> 3) & 1) * 8 + (lane & 7);  // A rows
    const int selA    = lane >> 4;                           // A k-half
    const int rowoffB = (lane >> 4) * 8 + (lane & 7);        // B rows
    const int selB    = (lane >> 3) & 1;                     // B k-half
    const int sw      = lane & 7;

    const uint32_t sKg = sb + (g01 ? KBB : KAB);
    const uint32_t sVg = sb + (g01 ? VBB : VAB);
    const uint32_t sPg = sb + (g01 ? PBB : PAB);

    // ---- prologue: all warps stage Q; S warps cp K(g01); PV warps cp V(g01) ----
#pragma unroll
    for (int it = 0; it < 2; it++) {
        int job = wid + 16 * it;                 // 32 jobs: tg 0..1 x fg 0..15
        int tg = job >> 4, fg = job & 15;
        int m = tg * 32 + lane;
        const float* gp = Qg + (size_t)(fg * 8) * 1024 + m;
        float f[8];
#pragma unroll
        for (int j = 0; j < 8; j++) f[j] = gp[(size_t)j * 1024];
        uint32_t a = sb + QB + (uint32_t)(m * 256 + ((fg ^ (m & 7)) << 4));
        sts128(a, h2bits(f[0], f[1]), h2bits(f[2], f[3]),
                  h2bits(f[4], f[5]), h2bits(f[6], f[7]));
    }
    if (isS) { stage_K_async(g01, sKg, w4, lane); cp_commit(); }
    else     { stage_V_async(g01, sVg, w4, lane); cp_commit(); }
    __syncthreads();

    if (isS) {
        // ===== S warps (32x64 tiles): S = Q K^T, softmax -> P =====
        const int qrow = (w4 >> 1) * 32;
        const int scol = (w4 & 1) * 64;
        const uint32_t qa0 = sb + QB + (uint32_t)((qrow + rowoff) * 256);
        const uint32_t qa1 = qa0 + 16 * 256;
        const uint32_t kb  = sKg + (uint32_t)((scol + rowoffB) * 256);
        float racc0[2] = {0.f, 0.f}, racc1[2] = {0.f, 0.f};

        for (int kt = g01; kt < NTILES; kt += 2) {
            cp_wait0();
            bar_sync(1 + g01, 128);              // K(kt) visible to group S warps

            float c[2][8][4];
#pragma unroll
            for (int mt = 0; mt < 2; mt++)
#pragma unroll
                for (int nt = 0; nt < 8; nt++)
#pragma unroll
                    for (int r = 0; r < 4; r++) c[mt][nt][r] = 0.f;

#pragma unroll
            for (int ks = 0; ks < 8; ks++) {
                const uint32_t ua = (uint32_t)(((2 * ks + selA) ^ sw) << 4);
                const uint32_t ub = (uint32_t)(((2 * ks + selB) ^ sw) << 4);
                uint32_t a0[4], a1[4], b[4][4];
                ldsm4(a0, qa0 + ua);
                ldsm4(a1, qa1 + ua);
                ldsm4(b[0], kb + ub);
                ldsm4(b[1], kb + 16 * 256 + ub);
                ldsm4(b[2], kb + 32 * 256 + ub);
                ldsm4(b[3], kb + 48 * 256 + ub);
#pragma unroll
                for (int nb = 0; nb < 4; nb++) {
                    mma16(c[0][2 * nb],     a0, b[nb] + 0);
                    mma16(c[0][2 * nb + 1], a0, b[nb] + 2);
                    mma16(c[1][2 * nb],     a1, b[nb] + 0);
                    mma16(c[1][2 * nb + 1], a1, b[nb] + 2);
                }
            }
            bar_sync(3 + g01, 128);              // group S warps done reading K
            if (kt + 2 < NTILES) { stage_K_async(kt + 2, sKg, w4, lane); cp_commit(); }

            if (kt >= 2) bar_sync(5 + g01, 256); // P buffer free (PV(kt-2) done)

#pragma unroll
            for (int mt = 0; mt < 2; mt++) {
                float s0 = 0.f, s1 = 0.f;
                const int row = qrow + mt * 16 + g;
#pragma unroll
                for (int nt = 0; nt < 8; nt++) {
                    float e0 = __expf(c[mt][nt][0] * SCALE);
                    float e1 = __expf(c[mt][nt][1] * SCALE);
                    float e2 = __expf(c[mt][nt][2] * SCALE);
                    float e3 = __expf(c[mt][nt][3] * SCALE);
                    uint32_t u01 = h2bits(e0, e1);
                    uint32_t u23 = h2bits(e2, e3);
                    s0 += h2sum(u01); s1 += h2sum(u23);
                    const int unit = (scol >> 3) + nt;
                    sts32(sPg + (uint32_t)(row * 256 + ((unit ^ g) << 4) + 4 * t4), u01);
                    sts32(sPg + (uint32_t)((row + 8) * 256 + ((unit ^ g) << 4) + 4 * t4), u23);
                }
                s0 += __shfl_xor_sync(0xffffffffu, s0, 1);
                s0 += __shfl_xor_sync(0xffffffffu, s0, 2);
                s1 += __shfl_xor_sync(0xffffffffu, s1, 1);
                s1 += __shfl_xor_sync(0xffffffffu, s1, 2);
                racc0[mt] += s0; racc1[mt] += s1;
            }
            bar_arrive(7 + g01, 256);            // P(kt) full
        }

        if (t4 == 0) {
#pragma unroll
            for (int mt = 0; mt < 2; mt++) {
                const int row = qrow + mt * 16 + g;
                smf[RS4W + row * 4 + g01 * 2 + (w4 & 1)]       = racc0[mt];
                smf[RS4W + (row + 8) * 4 + g01 * 2 + (w4 & 1)] = racc1[mt];
            }
        }
        __syncthreads();                          // epilogue join (1)
        if (tid < 64) {
            const float* r4 = smf + RS4W + tid * 4;
            smf[RSW + tid] = 1.0f / ((r4[0] + r4[1]) + (r4[2] + r4[3]));
        }
        __syncthreads();                          // epilogue join (2)
    } else {
        // ===== PV warps (64x32 tiles): O^T += V P^T over group's kt =====
        const int vrow = (w4 >> 1) * 64;
        const int mcol = (w4 & 1) * 32;
        const uint32_t va  = sVg + (uint32_t)((vrow + rowoff) * 256);
        const uint32_t pbb = sPg + (uint32_t)((mcol + rowoffB) * 256);

        float o[4][4][4];
#pragma unroll
        for (int a = 0; a < 4; a++)
#pragma unroll
            for (int b = 0; b < 4; b++)
#pragma unroll
                for (int r = 0; r < 4; r++) o[a][b][r] = 0.f;

        for (int kt = g01; kt < NTILES; kt += 2) {
            bar_sync(7 + g01, 256);              // P(kt) full
            cp_wait0();
            bar_sync(9 + g01, 128);              // V(kt) visible to group PV warps

#pragma unroll
            for (int ks = 0; ks < 8; ks++) {
                const uint32_t ua = (uint32_t)(((2 * ks + selA) ^ sw) << 4);
                const uint32_t ub = (uint32_t)(((2 * ks + selB) ^ sw) << 4);
                uint32_t a[4][4], b0[4];
                ldsm4(a[0], va + ua);
                ldsm4(a[1], va + 16 * 256 + ua);
                ldsm4(a[2], va + 32 * 256 + ua);
                ldsm4(a[3], va + 48 * 256 + ua);
                ldsm4(b0, pbb + ub);
#pragma unroll
                for (int vt = 0; vt < 4; vt++) {
                    mma16(o[vt][0], a[vt], b0 + 0);
                    mma16(o[vt][1], a[vt], b0 + 2);
                }
                uint32_t b1[4];
                ldsm4(b1, pbb + 16 * 256 + ub);
#pragma unroll
                for (int vt = 0; vt < 4; vt++) {
                    mma16(o[vt][2], a[vt], b1 + 0);
                    mma16(o[vt][3], a[vt], b1 + 2);
                }
            }
            bar_arrive(5 + g01, 256);            // P(kt) free
            bar_sync(11 + g01, 128);             // group PV warps done reading V
            if (kt + 2 < NTILES) { stage_V_async(kt + 2, sVg, w4, lane); cp_commit(); }
        }

        __syncthreads();                          // epilogue join (1)
        if (g01 == 0) {
            // group A: park partial O in smem (K buffers are dead now)
#pragma unroll
            for (int bn = 0; bn < 4; bn++) {
                const int m0 = mcol + bn * 8 + 2 * t4;
#pragma unroll
                for (int vt = 0; vt < 4; vt++) {
                    const int v = vrow + vt * 16 + g;
                    *(float2*)(smf + OCW + v * OST + m0) =
                        make_float2(o[vt][bn][0], o[vt][bn][1]);
                    *(float2*)(smf + OCW + (v + 8) * OST + m0) =
                        make_float2(o[vt][bn][2], o[vt][bn][3]);
                }
            }
        }
        __syncthreads();                          // epilogue join (2)
        if (g01 == 1) {
            // group B: combine + normalize + store
            float* Og = out + (size_t)bq * 131072u + sq0;
#pragma unroll
            for (int bn = 0; bn < 4; bn++) {
                const int m0 = mcol + bn * 8 + 2 * t4;
                const float i0 = smf[RSW + m0], i1 = smf[RSW + m0 + 1];
#pragma unroll
                for (int vt = 0; vt < 4; vt++) {
                    const int v = vrow + vt * 16 + g;
                    float2 a0 = *(const float2*)(smf + OCW + v * OST + m0);
                    float2 a1 = *(const float2*)(smf + OCW + (v + 8) * OST + m0);
                    *(float2*)(Og + (size_t)v * 1024 + m0) =
                        make_float2((a0.x + o[vt][bn][0]) * i0,
                                    (a0.y + o[vt][bn][1]) * i1);
                    *(float2*)(Og + (size_t)(v + 8) * 1024 + m0) =
                        make_float2((a1.x + o[vt][bn][2]) * i0,
                                    (a1.y + o[vt][bn][3]) * i1);
                }
            }
        }
    }
}

extern "C" void kernel_launch(void* const* d_in, const int* in_sizes, int n_in,
                              void* d_out, int out_size) {
    (void)in_sizes; (void)n_in; (void)out_size;
    const float* x = (const float*)d_in[0];
    float* out = (float*)d_out;
    cudaFuncSetAttribute(conv_attn_kernel,
                         cudaFuncAttributeMaxDynamicSharedMemorySize, SMEM_BYTES);
    prepass_kernel<<<64, 256>>>(x);
    conv_attn_kernel<<<128, 512, SMEM_BYTES>>>(x, out);
}

// round 15
// speedup vs baseline: 1.6713x; 1.0394x over previous
#include <cuda_runtime.h>
#include <cuda_fp16.h>
#include <cstdint>

// N=8192 tokens, D=128, x layout [8,384,32,32] fp32 (feature-major)
#define NTILES 64
#define SCALE 0.08838834764831845f  // 1/sqrt(128)

// byte offsets in dynamic smem; all fp16 tiles row=256B, XOR-swizzled 16B units
#define QB    0u        // Q  [m 64][k=feat 128]
#define KAB   16384u    // K group A
#define KBB   49152u    // K group B
#define VAB   81920u    // V group A
#define VBB   114688u   // V group B
#define PA0B  147456u   // P group A, slot 0
#define PA1B  163840u   // P group A, slot 1
#define PB0B  180224u   // P group B, slot 0
#define PB1B  196608u   // P group B, slot 1
#define SMEM_BYTES 214272
#define RS4W  53248     // word idx: 64 x 4 partial rowsums (A0,A1,B0,B1)
#define RSW   53504     // word idx: 64 inverse rowsums
#define OCW   4096      // word idx: epilogue O-combine scratch (reuses K buffers)
#define OST   68        // O-combine row stride (floats)

// barrier ids:
//  0: __syncthreads
//  1+g01        (128): K staged-visible / readers-done (2 rendezvous per iter)
//  3+g01        (128): V staged-visible / readers-done
//  5+g01*2+slot (256): P(slot) full   (S arrives, PV syncs)
//  9+g01*2+slot (256): P(slot) free   (PV arrives, S syncs from 2nd use)

// one-time fp16 scratch (prepass output)
__device__ __half g_kt[8192 * 128];      // K^T: [token][feature]
__device__ __half g_v[8 * 128 * 1024];   // V:   [batch][feature][token]

extern __shared__ float smdyn[];

__device__ __forceinline__ uint32_t smem_u32(const void* p) {
    uint32_t a;
    asm("{ .reg .u64 t; cvta.to.shared.u64 t, %1; cvt.u32.u64 %0, t; }" : "=r"(a) : "l"(p));
    return a;
}
__device__ __forceinline__ void bar_sync(int id, int cnt) {
    asm volatile("bar.sync %0, %1;" :: "r"(id), "r"(cnt) : "memory");
}
__device__ __forceinline__ void bar_arrive(int id, int cnt) {
    asm volatile("bar.arrive %0, %1;" :: "r"(id), "r"(cnt) : "memory");
}
__device__ __forceinline__ uint32_t h2bits(float a, float b) {
    __half2 h = __floats2half2_rn(a, b);
    return *reinterpret_cast<uint32_t*>(&h);
}
__device__ __forceinline__ float h2sum(uint32_t u) {
    __half2 h = *reinterpret_cast<__half2*>(&u);
    float2 f = __half22float2(h);
    return f.x + f.y;
}
__device__ __forceinline__ void sts128(uint32_t a, uint32_t u0, uint32_t u1,
                                       uint32_t u2, uint32_t u3) {
    asm volatile("st.shared.v4.b32 [%0], {%1,%2,%3,%4};"
                 :: "r"(a), "r"(u0), "r"(u1), "r"(u2), "r"(u3) : "memory");
}
__device__ __forceinline__ void sts32(uint32_t a, uint32_t u0) {
    asm volatile("st.shared.b32 [%0], %1;" :: "r"(a), "r"(u0) : "memory");
}
__device__ __forceinline__ void ldsm4(uint32_t r[4], uint32_t addr) {
    asm volatile("ldmatrix.sync.aligned.m8n8.x4.shared.b16 {%0,%1,%2,%3}, [%4];"
                 : "=r"(r[0]), "=r"(r[1]), "=r"(r[2]), "=r"(r[3]) : "r"(addr));
}
__device__ __forceinline__ void mma16(float c[4], const uint32_t a[4], const uint32_t b[2]) {
    asm volatile("mma.sync.aligned.m16n8k16.row.col.f32.f16.f16.f32 "
                 "{%0,%1,%2,%3}, {%4,%5,%6,%7}, {%8,%9}, {%0,%1,%2,%3};"
                 : "+f"(c[0]), "+f"(c[1]), "+f"(c[2]), "+f"(c[3])
                 : "r"(a[0]), "r"(a[1]), "r"(a[2]), "r"(a[3]),
                   "r"(b[0]), "r"(b[1]));
}
__device__ __forceinline__ void cp16h(uint32_t dst, const __half* src) {
    asm volatile("cp.async.cg.shared.global [%0], [%1], 16;" :: "r"(dst), "l"(src));
}
__device__ __forceinline__ void cp_commit() { asm volatile("cp.async.commit_group;"); }
__device__ __forceinline__ void cp_wait0()  { asm volatile("cp.async.wait_group 0;"); }

// ================= prepass: x fp32 -> fp16 scratch (K transposed) =================
__global__ void __launch_bounds__(256) prepass_kernel(const float* __restrict__ x) {
    const int tid  = blockIdx.x * 256 + threadIdx.x;   // 0..16383
    const int wid  = tid >> 5;                          // 0..511
    const int lane = threadIdx.x & 31;

#pragma unroll
    for (int i = 0; i < 8; i++) {
        int job = wid * 8 + i;
        int tb = job >> 4, fg = job & 15;
        int b = tb >> 5;
        int t = (tb & 31) * 32 + lane;
        const float* gp = x + (size_t)b * 393216u + (size_t)(128 + fg * 8) * 1024u + t;
        float f[8];
#pragma unroll
        for (int j = 0; j < 8; j++) f[j] = gp[(size_t)j * 1024];
        uint4 u;
        u.x = h2bits(f[0], f[1]); u.y = h2bits(f[2], f[3]);
        u.z = h2bits(f[4], f[5]); u.w = h2bits(f[6], f[7]);
        *(uint4*)(&g_kt[(size_t)((b * 1024 + t) * 128 + fg * 8)]) = u;
    }
#pragma unroll
    for (int i = 0; i < 8; i++) {
        int e = (i * 16384 + tid) * 8;
        int b = e >> 17;
        int r = e & 131071;
        const float* gp = x + (size_t)b * 393216u + r;
        float4 a0 = *(const float4*)gp;
        float4 a1 = *(const float4*)(gp + 4);
        uint4 u;
        u.x = h2bits(a0.x, a0.y); u.y = h2bits(a0.z, a0.w);
        u.z = h2bits(a1.x, a1.y); u.w = h2bits(a1.z, a1.w);
        *(uint4*)(&g_v[e]) = u;
    }
}

// ---- staging: cp.async fp16 scratch -> swizzled smem (4 warps per array) ----
__device__ __forceinline__ void stage_K_async(int kt, uint32_t skb, int pr, int lane) {
#pragma unroll
    for (int i = 0; i < 16; i++) {
        int id = pr * 512 + i * 32 + lane;      // 0..2047 16B-units
        int n = id >> 4, fg = id & 15;
        cp16h(skb + (uint32_t)(n * 256 + ((fg ^ (n & 7)) << 4)),
              g_kt + (size_t)((kt * 128 + n) * 128 + fg * 8));
    }
}
__device__ __forceinline__ void stage_V_async(int kt, uint32_t svb, int pr, int lane) {
    const int bv = kt >> 3, tof = (kt & 7) << 7;
#pragma unroll
    for (int i = 0; i < 16; i++) {
        int id = pr * 512 + i * 32 + lane;
        int v = id >> 4, u = id & 15;
        cp16h(svb + (uint32_t)(v * 256 + ((u ^ (v & 7)) << 4)),
              g_v + (size_t)((bv * 128 + v) * 1024 + tof + u * 8));
    }
}

__global__ void __launch_bounds__(512, 1)
conv_attn_kernel(const float* __restrict__ x, float* __restrict__ out) {
    const int tid  = threadIdx.x;
    const int lane = tid & 31;
    const int wid  = tid >> 5;
    const int g    = lane >> 2;
    const int t4   = lane & 3;
    const uint32_t sb = smem_u32(smdyn);
    float* smf = smdyn;

    const int g01  = wid >> 3;                 // 0 = group A (even kt), 1 = B (odd kt)
    const int w4   = wid & 3;
    const bool isS = (wid & 7) < 4;

    const int bq  = blockIdx.x >> 4;
    const int sq0 = (blockIdx.x & 15) << 6;
    const float* Qg = x + (size_t)bq * 393216u + 262144u + sq0;

    // ldmatrix per-lane decomposition
    const int rowoff  = ((lane >> 3) & 1) * 8 + (lane & 7);  // A rows
    const int selA    = lane >> 4;                           // A k-half
    const int rowoffB = (lane >> 4) * 8 + (lane & 7);        // B rows
    const int selB    = (lane >> 3) & 1;                     // B k-half
    const int sw      = lane & 7;

    const uint32_t sKg   = sb + (g01 ? KBB : KAB);
    const uint32_t sVg   = sb + (g01 ? VBB : VAB);
    const uint32_t sPgrp = sb + (g01 ? PB0B : PA0B);   // + slot<<14

    // ---- prologue: all warps stage Q; S warps cp K(g01); PV warps cp V(g01) ----
#pragma unroll
    for (int it = 0; it < 2; it++) {
        int job = wid + 16 * it;                 // 32 jobs: tg 0..1 x fg 0..15
        int tg = job >> 4, fg = job & 15;
        int m = tg * 32 + lane;
        const float* gp = Qg + (size_t)(fg * 8) * 1024 + m;
        float f[8];
#pragma unroll
        for (int j = 0; j < 8; j++) f[j] = gp[(size_t)j * 1024];
        uint32_t a = sb + QB + (uint32_t)(m * 256 + ((fg ^ (m & 7)) << 4));
        sts128(a, h2bits(f[0], f[1]), h2bits(f[2], f[3]),
                  h2bits(f[4], f[5]), h2bits(f[6], f[7]));
    }
    if (isS) { stage_K_async(g01, sKg, w4, lane); cp_commit(); }
    else     { stage_V_async(g01, sVg, w4, lane); cp_commit(); }
    __syncthreads();

    if (isS) {
        // ===== S warps (32x64 tiles): S = Q K^T, softmax -> P (2 slots) =====
        const int qrow = (w4 >> 1) * 32;
        const int scol = (w4 & 1) * 64;
        const uint32_t qa0 = sb + QB + (uint32_t)((qrow + rowoff) * 256);
        const uint32_t qa1 = qa0 + 16 * 256;
        const uint32_t kb  = sKg + (uint32_t)((scol + rowoffB) * 256);
        float racc0[2] = {0.f, 0.f}, racc1[2] = {0.f, 0.f};

        for (int kt = g01; kt < NTILES; kt += 2) {
            const int slot = (kt >> 1) & 1;
            cp_wait0();
            bar_sync(1 + g01, 128);              // K(kt) visible (rendezvous 1)

            float c[2][8][4];
#pragma unroll
            for (int mt = 0; mt < 2; mt++)
#pragma unroll
                for (int nt = 0; nt < 8; nt++)
#pragma unroll
                    for (int r = 0; r < 4; r++) c[mt][nt][r] = 0.f;

#pragma unroll
            for (int ks = 0; ks < 8; ks++) {
                const uint32_t ua = (uint32_t)(((2 * ks + selA) ^ sw) << 4);
                const uint32_t ub = (uint32_t)(((2 * ks + selB) ^ sw) << 4);
                uint32_t a0[4], a1[4], b[4][4];
                ldsm4(a0, qa0 + ua);
                ldsm4(a1, qa1 + ua);
                ldsm4(b[0], kb + ub);
                ldsm4(b[1], kb + 16 * 256 + ub);
                ldsm4(b[2], kb + 32 * 256 + ub);
                ldsm4(b[3], kb + 48 * 256 + ub);
#pragma unroll
                for (int nb = 0; nb < 4; nb++) {
                    mma16(c[0][2 * nb],     a0, b[nb] + 0);
                    mma16(c[0][2 * nb + 1], a0, b[nb] + 2);
                    mma16(c[1][2 * nb],     a1, b[nb] + 0);
                    mma16(c[1][2 * nb + 1], a1, b[nb] + 2);
                }
            }
            bar_sync(1 + g01, 128);              // K readers done (rendezvous 2)
            if (kt + 2 < NTILES) { stage_K_async(kt + 2, sKg, w4, lane); cp_commit(); }

            if (kt >= 4) bar_sync(9 + g01 * 2 + slot, 256);  // P slot free (PV(kt-4) done)

            const uint32_t sPg = sPgrp + (uint32_t)(slot << 14);
#pragma unroll
            for (int mt = 0; mt < 2; mt++) {
                float s0 = 0.f, s1 = 0.f;
                const int row = qrow + mt * 16 + g;
#pragma unroll
                for (int nt = 0; nt < 8; nt++) {
                    float e0 = __expf(c[mt][nt][0] * SCALE);
                    float e1 = __expf(c[mt][nt][1] * SCALE);
                    float e2 = __expf(c[mt][nt][2] * SCALE);
                    float e3 = __expf(c[mt][nt][3] * SCALE);
                    uint32_t u01 = h2bits(e0, e1);
                    uint32_t u23 = h2bits(e2, e3);
                    s0 += h2sum(u01); s1 += h2sum(u23);
                    const int unit = (scol >> 3) + nt;
                    sts32(sPg + (uint32_t)(row * 256 + ((unit ^ g) << 4) + 4 * t4), u01);
                    sts32(sPg + (uint32_t)((row + 8) * 256 + ((unit ^ g) << 4) + 4 * t4), u23);
                }
                s0 += __shfl_xor_sync(0xffffffffu, s0, 1);
                s0 += __shfl_xor_sync(0xffffffffu, s0, 2);
                s1 += __shfl_xor_sync(0xffffffffu, s1, 1);
                s1 += __shfl_xor_sync(0xffffffffu, s1, 2);
                racc0[mt] += s0; racc1[mt] += s1;
            }
            bar_arrive(5 + g01 * 2 + slot, 256); // P(kt) full
        }

        if (t4 == 0) {
#pragma unroll
            for (int mt = 0; mt < 2; mt++) {
                const int row = qrow + mt * 16 + g;
                smf[RS4W + row * 4 + g01 * 2 + (w4 & 1)]       = racc0[mt];
                smf[RS4W + (row + 8) * 4 + g01 * 2 + (w4 & 1)] = racc1[mt];
            }
        }
        __syncthreads();                          // epilogue join (1)
        if (tid < 64) {
            const float* r4 = smf + RS4W + tid * 4;
            smf[RSW + tid] = 1.0f / ((r4[0] + r4[1]) + (r4[2] + r4[3]));
        }
        __syncthreads();                          // epilogue join (2)
    } else {
        // ===== PV warps (64x32 tiles): O^T += V P^T over group's kt =====
        const int vrow = (w4 >> 1) * 64;
        const int mcol = (w4 & 1) * 32;
        const uint32_t va    = sVg + (uint32_t)((vrow + rowoff) * 256);
        const uint32_t pboff = (uint32_t)((mcol + rowoffB) * 256);

        float o[4][4][4];
#pragma unroll
        for (int a = 0; a < 4; a++)
#pragma unroll
            for (int b = 0; b < 4; b++)
#pragma unroll
                for (int r = 0; r < 4; r++) o[a][b][r] = 0.f;

        for (int kt = g01; kt < NTILES; kt += 2) {
            const int slot = (kt >> 1) & 1;
            bar_sync(5 + g01 * 2 + slot, 256);   // P(kt) full
            cp_wait0();
            bar_sync(3 + g01, 128);              // V(kt) visible (rendezvous 1)

            const uint32_t pbb = sPgrp + (uint32_t)(slot << 14) + pboff;
#pragma unroll
            for (int ks = 0; ks < 8; ks++) {
                const uint32_t ua = (uint32_t)(((2 * ks + selA) ^ sw) << 4);
                const uint32_t ub = (uint32_t)(((2 * ks + selB) ^ sw) << 4);
                uint32_t a[4][4], b0[4];
                ldsm4(a[0], va + ua);
                ldsm4(a[1], va + 16 * 256 + ua);
                ldsm4(a[2], va + 32 * 256 + ua);
                ldsm4(a[3], va + 48 * 256 + ua);
                ldsm4(b0, pbb + ub);
#pragma unroll
                for (int vt = 0; vt < 4; vt++) {
                    mma16(o[vt][0], a[vt], b0 + 0);
                    mma16(o[vt][1], a[vt], b0 + 2);
                }
                uint32_t b1[4];
                ldsm4(b1, pbb + 16 * 256 + ub);
#pragma unroll
                for (int vt = 0; vt < 4; vt++) {
                    mma16(o[vt][2], a[vt], b1 + 0);
                    mma16(o[vt][3], a[vt], b1 + 2);
                }
            }
            bar_arrive(9 + g01 * 2 + slot, 256); // P(kt) slot free
            bar_sync(3 + g01, 128);              // V readers done (rendezvous 2)
            if (kt + 2 < NTILES) { stage_V_async(kt + 2, sVg, w4, lane); cp_commit(); }
        }

        __syncthreads();                          // epilogue join (1)
        if (g01 == 0) {
            // group A: park partial O in smem (K buffers are dead now)
#pragma unroll
            for (int bn = 0; bn < 4; bn++) {
                const int m0 = mcol + bn * 8 + 2 * t4;
#pragma unroll
                for (int vt = 0; vt < 4; vt++) {
                    const int v = vrow + vt * 16 + g;
                    *(float2*)(smf + OCW + v * OST + m0) =
                        make_float2(o[vt][bn][0], o[vt][bn][1]);
                    *(float2*)(smf + OCW + (v + 8) * OST + m0) =
                        make_float2(o[vt][bn][2], o[vt][bn][3]);
                }
            }
        }
        __syncthreads();                          // epilogue join (2)
        if (g01 == 1) {
            // group B: combine + normalize + store
            float* Og = out + (size_t)bq * 131072u + sq0;
#pragma unroll
            for (int bn = 0; bn < 4; bn++) {
                const int m0 = mcol + bn * 8 + 2 * t4;
                const float i0 = smf[RSW + m0], i1 = smf[RSW + m0 + 1];
#pragma unroll
                for (int vt = 0; vt < 4; vt++) {
                    const int v = vrow + vt * 16 + g;
                    float2 a0 = *(const float2*)(smf + OCW + v * OST + m0);
                    float2 a1 = *(const float2*)(smf + OCW + (v + 8) * OST + m0);
                    *(float2*)(Og + (size_t)v * 1024 + m0) =
                        make_float2((a0.x + o[vt][bn][0]) * i0,
                                    (a0.y + o[vt][bn][1]) * i1);
                    *(float2*)(Og + (size_t)(v + 8) * 1024 + m0) =
                        make_float2((a1.x + o[vt][bn][2]) * i0,
                                    (a1.y + o[vt][bn][3]) * i1);
                }
            }
        }
    }
}

extern "C" void kernel_launch(void* const* d_in, const int* in_sizes, int n_in,
                              void* d_out, int out_size) {
    (void)in_sizes; (void)n_in; (void)out_size;
    const float* x = (const float*)d_in[0];
    float* out = (float*)d_out;
    cudaFuncSetAttribute(conv_attn_kernel,
                         cudaFuncAttributeMaxDynamicSharedMemorySize, SMEM_BYTES);
    prepass_kernel<<<64, 256>>>(x);
    conv_attn_kernel<<<128, 512, SMEM_BYTES>>>(x, out);
}